// round 1
// baseline (speedup 1.0000x reference)
#include <cuda_runtime.h>
#include <cuda_bf16.h>
#include <math.h>

// ---------------- problem constants ----------------
#define LAYERS 4
#define NH     128
#define FC     16
#define HP     16
#define WP     16
#define BB     16
#define TT     20
#define PRE    10
#define NPOS   256            // 16*16
#define NSTEP  19             // T-1
#define OUT_FRAMES (BB*NSTEP*HP*WP*FC)   // 1245184

typedef unsigned long long ull;

// ---------------- device scratch (no allocations allowed) ----------------
__device__ float g_h[2][LAYERS][BB*NH*NPOS];
__device__ float g_c[2][LAYERS][BB*NH*NPOS];
__device__ float g_x0[BB*FC*NPOS];
__device__ float g_xg[BB*FC*NPOS];
__device__ float g_gx[BB*4*NH*NPOS];
__device__ float g_gh[BB*4*NH*NPOS];
__device__ float g_WxT0[FC*25*512];
__device__ float g_WxT[3][NH*25*512];
__device__ float g_WhT[4][NH*25*512];
__device__ float g_acc[2];

// ---------------- helpers ----------------
__device__ __forceinline__ ull pack2(float v) {
    ull r;
    asm("mov.b64 %0, {%1, %1};" : "=l"(r) : "r"(__float_as_uint(v)));
    return r;
}
__device__ __forceinline__ ull fma2(ull a, ull b, ull c) {
    ull d;
    asm("fma.rn.f32x2 %0, %1, %2, %3;" : "=l"(d) : "l"(a), "l"(b), "l"(c));
    return d;
}
__device__ __forceinline__ float lo32(ull a) { return __uint_as_float((unsigned)(a & 0xffffffffull)); }
__device__ __forceinline__ float hi32(ull a) { return __uint_as_float((unsigned)(a >> 32)); }
__device__ __forceinline__ float sigmoidf_(float x) { return 1.f / (1.f + expf(-x)); }

// ---------------- zero fill ----------------
__global__ void zero_k(float* p, int n) {
    int i = blockIdx.x * blockDim.x + threadIdx.x;
    if (i < n) p[i] = 0.f;
}

// ---------------- weight transpose:  W[g*128+hc][cin][5][5] -> Wt[cin*25+tap][hc*4+g] --------
__global__ void transpose_w(const float* __restrict__ W, float* __restrict__ Wt, int CIN) {
    int idx = blockIdx.x * 256 + threadIdx.x;
    int total = 512 * CIN * 25;
    if (idx >= total) return;
    int col = idx & 511;
    int row = idx >> 9;
    int hc = col >> 2, g = col & 3;
    int cin = row / 25, tap = row % 25;
    Wt[idx] = W[(((g * NH + hc) * CIN) + cin) * 25 + tap];
}

// ---------------- conv: gates[b][512][256] = Wt * in[b][CIN][256], 5x5 SAME ----------------
// block: 128 threads; thread -> positions p and p+128; 8 hidden-ch tile (32 gate channels)
// grid: (16 hcTiles, 16 batch)
#define CHUNK 8
template<int CIN>
__global__ __launch_bounds__(128) void conv_gates(
    const float* __restrict__ in,   // [B][CIN][256]
    const float* __restrict__ Wt,   // [CIN*25][512]
    float* __restrict__ gout)       // [B][512][256], channel = hc*4+gate
{
    const int b    = blockIdx.y;
    const int gch0 = blockIdx.x * 32;       // 8 hidden ch * 4 gates
    const int tid  = threadIdx.x;

    const int p0 = tid;                     // rows 0..7
    const int y0 = p0 >> 4, x0c = p0 & 15;  // p1 = p0+128 -> y0+8, same x

    __shared__ float s_in[CHUNK][400];      // 20x20 padded
    __shared__ ull   s_w2[CHUNK * 25 * 16]; // 32 floats per tap as 16 pairs

    ull acc0[16], acc1[16];
#pragma unroll
    for (int j = 0; j < 16; j++) { acc0[j] = 0ull; acc1[j] = 0ull; }

    for (int c0 = 0; c0 < CIN; c0 += CHUNK) {
        // stage input: CHUNK x 400
        for (int i = tid; i < CHUNK * 400; i += 128) {
            int c = i / 400, r = i - c * 400;
            int iy = r / 20 - 2, ix = r - (r / 20) * 20 - 2;
            float v = 0.f;
            if (iy >= 0 && iy < 16 && ix >= 0 && ix < 16)
                v = in[((b * CIN) + c0 + c) * NPOS + iy * 16 + ix];
            s_in[c][r] = v;
        }
        // stage weights: CHUNK*25 rows x 32 cols
        float* s_wf = reinterpret_cast<float*>(s_w2);
        for (int i = tid; i < CHUNK * 25 * 32; i += 128) {
            int row = i >> 5, j = i & 31;
            s_wf[i] = Wt[(c0 * 25 + row) * 512 + gch0 + j];
        }
        __syncthreads();

        for (int c = 0; c < CHUNK; c++) {
#pragma unroll
            for (int ky = 0; ky < 5; ky++) {
                const float* rin0 = &s_in[c][(y0 + ky) * 20 + x0c];
                const float* rin1 = rin0 + 160;   // +8 rows
#pragma unroll
                for (int kx = 0; kx < 5; kx++) {
                    ull vv0 = pack2(rin0[kx]);
                    ull vv1 = pack2(rin1[kx]);
                    const ull* wp = &s_w2[(c * 25 + ky * 5 + kx) * 16];
#pragma unroll
                    for (int j = 0; j < 16; j++) {
                        ull w = wp[j];
                        acc0[j] = fma2(vv0, w, acc0[j]);
                        acc1[j] = fma2(vv1, w, acc1[j]);
                    }
                }
            }
        }
        __syncthreads();
    }

    float* outb = gout + (size_t)b * 512 * NPOS;
#pragma unroll
    for (int j = 0; j < 16; j++) {
        outb[(gch0 + 2 * j)     * NPOS + p0]       = lo32(acc0[j]);
        outb[(gch0 + 2 * j + 1) * NPOS + p0]       = hi32(acc0[j]);
        outb[(gch0 + 2 * j)     * NPOS + p0 + 128] = lo32(acc1[j]);
        outb[(gch0 + 2 * j + 1) * NPOS + p0 + 128] = hi32(acc1[j]);
    }
}

// ---------------- pointwise LSTM ----------------
__global__ void lstm_pw(const float* __restrict__ gx, const float* __restrict__ gh,
                        const float* __restrict__ c_prev,
                        float* __restrict__ c_new, float* __restrict__ h_new)
{
    int idx = blockIdx.x * 256 + threadIdx.x;       // b(4b) hc(7b) pos(8b)
    if (idx >= BB * NH * NPOS) return;
    int pos = idx & 255;
    int hc  = (idx >> 8) & 127;
    int b   = idx >> 15;
    int base = (b * 512 + hc * 4) * NPOS + pos;
    float ig = gx[base]            + gh[base];
    float fg = gx[base + NPOS]     + gh[base + NPOS];
    float gg = gx[base + 2 * NPOS] + gh[base + 2 * NPOS];
    float og = gx[base + 3 * NPOS] + gh[base + 3 * NPOS];
    float c  = sigmoidf_(fg + 1.0f) * c_prev[idx] + sigmoidf_(ig) * tanhf(gg);
    c_new[idx] = c;
    h_new[idx] = sigmoidf_(og) * tanhf(c);
}

// ---------------- 1x1 projection + output store ----------------
__global__ void xgen_k(const float* __restrict__ h3, const float* __restrict__ Wlast,
                       float* __restrict__ xg, float* __restrict__ out, int t)
{
    __shared__ float s_w[FC * NH];
    int b = blockIdx.x, pos = threadIdx.x;
    for (int i = pos; i < FC * NH; i += 256) s_w[i] = Wlast[i];
    __syncthreads();
    float acc[FC];
#pragma unroll
    for (int f = 0; f < FC; f++) acc[f] = 0.f;
    for (int ch = 0; ch < NH; ch++) {
        float hv = h3[(b * NH + ch) * NPOS + pos];
#pragma unroll
        for (int f = 0; f < FC; f++) acc[f] += hv * s_w[f * NH + ch];
    }
    int y = pos >> 4, x = pos & 15;
#pragma unroll
    for (int f = 0; f < FC; f++) {
        xg[(b * FC + f) * NPOS + pos] = acc[f];
        out[((((size_t)b * NSTEP + t) * HP + y) * WP + x) * FC + f] = acc[f];
    }
}

// ---------------- masked input ----------------
__global__ void mask_k(const float* __restrict__ frames, const float* __restrict__ mask,
                       const float* __restrict__ xg, float* __restrict__ x0, int t)
{
    int idx = blockIdx.x * 256 + threadIdx.x;       // b(4) c(4) pos(8)
    if (idx >= BB * FC * NPOS) return;
    int pos = idx & 255;
    int c = (idx >> 8) & 15;
    int b = idx >> 12;
    int y = pos >> 4, x = pos & 15;
    float f = frames[((((size_t)b * TT + t) * HP + y) * WP + x) * FC + c];
    float v;
    if (t < PRE) {
        v = f;
    } else {
        float m  = mask[((((size_t)b * (NSTEP - PRE) + (t - PRE)) * HP + y) * WP + x) * FC + c];
        float xv = xg[(b * FC + c) * NPOS + pos];
        v = m * f + (1.f - m) * xv;
    }
    x0[(b * FC + c) * NPOS + pos] = v;
}

// ---------------- loss: MSE ----------------
__global__ void mse_k(const float* __restrict__ pred, const float* __restrict__ frames,
                      float* __restrict__ acc)
{
    __shared__ float s_red[256];
    float sum = 0.f;
    for (int idx = blockIdx.x * 256 + threadIdx.x; idx < OUT_FRAMES; idx += gridDim.x * 256) {
        int c = idx & 15; int r = idx >> 4;
        int x = r & 15; r >>= 4;
        int y = r & 15; r >>= 4;
        int t = r % NSTEP; int b = r / NSTEP;
        float d = pred[idx] - frames[((((size_t)b * TT + t + 1) * HP + y) * WP + x) * FC + c];
        sum += d * d;
    }
    s_red[threadIdx.x] = sum;
    __syncthreads();
    for (int s = 128; s > 0; s >>= 1) {
        if (threadIdx.x < s) s_red[threadIdx.x] += s_red[threadIdx.x + s];
        __syncthreads();
    }
    if (threadIdx.x == 0) atomicAdd(&acc[0], s_red[0]);
}

// ---------------- loss: softmax heuristic ----------------
__global__ void heur_k(const float* __restrict__ pred, const float* __restrict__ frames,
                       float* __restrict__ acc)
{
    int idx = threadIdx.x;                      // 0..303 -> (t, w)
    if (idx >= NSTEP * WP) return;
    int t = idx / WP, w = idx % WP;
    float xp = 0.f, xt = 0.f;
    for (int c = 0; c < FC; c++) {
        // pred path: softmax over b of pred[b][t][0][w][c]
        float vals[BB]; float mx = -1e30f;
        for (int b = 0; b < BB; b++) {
            vals[b] = pred[((((size_t)b * NSTEP + t) * HP + 0) * WP + w) * FC + c];
            mx = fmaxf(mx, vals[b]);
        }
        float s = 0.f, sw = 0.f;
        for (int b = 0; b < BB; b++) {
            float e = expf(vals[b] - mx);
            s += e; sw += e * (float)b;
        }
        xp += sw / s;
        // true path: frames[b][t+1][0][w][c]
        mx = -1e30f;
        for (int b = 0; b < BB; b++) {
            vals[b] = frames[((((size_t)b * TT + t + 1) * HP + 0) * WP + w) * FC + c];
            mx = fmaxf(mx, vals[b]);
        }
        s = 0.f; sw = 0.f;
        for (int b = 0; b < BB; b++) {
            float e = expf(vals[b] - mx);
            s += e; sw += e * (float)b;
        }
        xt += sw / s;
    }
    xp *= (1.f / FC); xt *= (1.f / FC);
    float d = xp - xt;
    atomicAdd(&acc[1], d * d);
}

__global__ void finalize_k(const float* __restrict__ acc, float* __restrict__ out_loss)
{
    out_loss[0] = acc[0] / (float)OUT_FRAMES + acc[1] / (float)(NSTEP * WP);
}

// ---------------- host orchestration ----------------
extern "C" void kernel_launch(void* const* d_in, const int* in_sizes, int n_in,
                              void* d_out, int out_size)
{
    const float* frames = (const float*)d_in[0];
    const float* maskp  = (const float*)d_in[1];
    const float* Wx[4]  = { (const float*)d_in[2], (const float*)d_in[4],
                            (const float*)d_in[6], (const float*)d_in[8] };
    const float* Wh[4]  = { (const float*)d_in[3], (const float*)d_in[5],
                            (const float*)d_in[7], (const float*)d_in[9] };
    const float* Wlast  = (const float*)d_in[10];
    float* out = (float*)d_out;

    void* p;
    cudaGetSymbolAddress(&p, g_h);    float* hbuf  = (float*)p;
    cudaGetSymbolAddress(&p, g_c);    float* cbuf  = (float*)p;
    cudaGetSymbolAddress(&p, g_x0);   float* x0b   = (float*)p;
    cudaGetSymbolAddress(&p, g_xg);   float* xgb   = (float*)p;
    cudaGetSymbolAddress(&p, g_gx);   float* gxb   = (float*)p;
    cudaGetSymbolAddress(&p, g_gh);   float* ghb   = (float*)p;
    cudaGetSymbolAddress(&p, g_WxT0); float* wxt0  = (float*)p;
    cudaGetSymbolAddress(&p, g_WxT);  float* wxt   = (float*)p;
    cudaGetSymbolAddress(&p, g_WhT);  float* wht   = (float*)p;
    cudaGetSymbolAddress(&p, g_acc);  float* accb  = (float*)p;

    const int LSZ = BB * NH * NPOS;            // per-layer h/c size
    const int LAYSTRIDE = NH * 25 * 512;

    // zero initial state (ping buffer 0) and loss accumulators
    zero_k<<<(LAYERS * LSZ + 255) / 256, 256>>>(hbuf, LAYERS * LSZ);
    zero_k<<<(LAYERS * LSZ + 255) / 256, 256>>>(cbuf, LAYERS * LSZ);
    zero_k<<<1, 32>>>(accb, 2);

    // transpose weights
    transpose_w<<<(512 * FC * 25 + 255) / 256, 256>>>(Wx[0], wxt0, FC);
    for (int l = 1; l < LAYERS; l++)
        transpose_w<<<(512 * NH * 25 + 255) / 256, 256>>>(Wx[l], wxt + (l - 1) * LAYSTRIDE, NH);
    for (int l = 0; l < LAYERS; l++)
        transpose_w<<<(512 * NH * 25 + 255) / 256, 256>>>(Wh[l], wht + l * LAYSTRIDE, NH);

    dim3 cgrid(16, BB);
    for (int t = 0; t < NSTEP; t++) {
        int r = t & 1, w = 1 - r;
        float* h_r = hbuf + (size_t)r * LAYERS * LSZ;
        float* h_w = hbuf + (size_t)w * LAYERS * LSZ;
        float* c_r = cbuf + (size_t)r * LAYERS * LSZ;
        float* c_w = cbuf + (size_t)w * LAYERS * LSZ;

        mask_k<<<(BB * FC * NPOS + 255) / 256, 256>>>(frames, maskp, xgb, x0b, t);

        for (int l = 0; l < LAYERS; l++) {
            const float* xin = (l == 0) ? x0b : (h_w + (size_t)(l - 1) * LSZ);
            if (l == 0)
                conv_gates<FC><<<cgrid, 128>>>(xin, wxt0, gxb);
            else
                conv_gates<NH><<<cgrid, 128>>>(xin, wxt + (l - 1) * LAYSTRIDE, gxb);
            conv_gates<NH><<<cgrid, 128>>>(h_r + (size_t)l * LSZ, wht + l * LAYSTRIDE, ghb);
            lstm_pw<<<(BB * NH * NPOS + 255) / 256, 256>>>(
                gxb, ghb, c_r + (size_t)l * LSZ,
                c_w + (size_t)l * LSZ, h_w + (size_t)l * LSZ);
        }
        xgen_k<<<BB, 256>>>(h_w + (size_t)3 * LSZ, Wlast, xgb, out, t);
    }

    mse_k<<<1024, 256>>>(out, frames, accb);
    heur_k<<<1, NSTEP * WP>>>(out, frames, accb);
    finalize_k<<<1, 1>>>(accb, out + (out_size - 1));
}

// round 2
// speedup vs baseline: 1.0037x; 1.0037x over previous
#include <cuda_runtime.h>
#include <cuda_bf16.h>
#include <math.h>

// ---------------- problem constants ----------------
#define LAYERS 4
#define NH     128
#define FC     16
#define HP     16
#define WP     16
#define BB     16
#define TT     20
#define PRE    10
#define NPOS   256            // 16*16
#define NSTEP  19             // T-1
#define OUT_FRAMES (BB*NSTEP*HP*WP*FC)   // 1245184

typedef unsigned long long ull;

// ---------------- device scratch (no allocations allowed) ----------------
__device__ float g_h[2][LAYERS][BB*NH*NPOS];
__device__ float g_c[2][LAYERS][BB*NH*NPOS];
__device__ float g_x0[BB*FC*NPOS];
__device__ float g_xg[BB*FC*NPOS];
__device__ float g_gx[BB*4*NH*NPOS];
__device__ float g_gh[BB*4*NH*NPOS];
__device__ float g_WxT0[FC*25*512];
__device__ float g_WxT[3][NH*25*512];
__device__ float g_WhT[4][NH*25*512];
__device__ float g_acc[2];

// ---------------- helpers ----------------
__device__ __forceinline__ ull pack2(float v) {
    ull r;
    asm("mov.b64 %0, {%1, %1};" : "=l"(r) : "r"(__float_as_uint(v)));
    return r;
}
__device__ __forceinline__ ull fma2(ull a, ull b, ull c) {
    ull d;
    asm("fma.rn.f32x2 %0, %1, %2, %3;" : "=l"(d) : "l"(a), "l"(b), "l"(c));
    return d;
}
__device__ __forceinline__ float lo32(ull a) { return __uint_as_float((unsigned)(a & 0xffffffffull)); }
__device__ __forceinline__ float hi32(ull a) { return __uint_as_float((unsigned)(a >> 32)); }
__device__ __forceinline__ float sigmoidf_(float x) { return 1.f / (1.f + expf(-x)); }

// ---------------- zero fill ----------------
__global__ void zero_k(float* p, int n) {
    int i = blockIdx.x * blockDim.x + threadIdx.x;
    if (i < n) p[i] = 0.f;
}

// ---------------- weight transpose:  W[g*128+hc][cin][5][5] -> Wt[cin*25+tap][hc*4+g] --------
__global__ void transpose_w(const float* __restrict__ W, float* __restrict__ Wt, int CIN) {
    int idx = blockIdx.x * 256 + threadIdx.x;
    int total = 512 * CIN * 25;
    if (idx >= total) return;
    int col = idx & 511;
    int row = idx >> 9;
    int hc = col >> 2, g = col & 3;
    int cin = row / 25, tap = row % 25;
    Wt[idx] = W[(((g * NH + hc) * CIN) + cin) * 25 + tap];
}

// ---------------- conv: gates[b][512][256] = Wt * in[b][CIN][256], 5x5 SAME ----------------
// block: 128 threads; thread -> positions p and p+128; 8 hidden-ch tile (32 gate channels)
// grid: (16 hcTiles, 16 batch)
#define CHUNK 8
template<int CIN>
__global__ __launch_bounds__(128) void conv_gates(
    const float* __restrict__ in,   // [B][CIN][256]
    const float* __restrict__ Wt,   // [CIN*25][512]
    float* __restrict__ gout)       // [B][512][256], channel = hc*4+gate
{
    const int b    = blockIdx.y;
    const int gch0 = blockIdx.x * 32;       // 8 hidden ch * 4 gates
    const int tid  = threadIdx.x;

    const int p0 = tid;                     // rows 0..7
    const int y0 = p0 >> 4, x0c = p0 & 15;  // p1 = p0+128 -> y0+8, same x

    __shared__ float s_in[CHUNK][400];      // 20x20 padded
    __shared__ ull   s_w2[CHUNK * 25 * 16]; // 32 floats per tap as 16 pairs

    ull acc0[16], acc1[16];
#pragma unroll
    for (int j = 0; j < 16; j++) { acc0[j] = 0ull; acc1[j] = 0ull; }

    for (int c0 = 0; c0 < CIN; c0 += CHUNK) {
        // stage input: CHUNK x 400
        for (int i = tid; i < CHUNK * 400; i += 128) {
            int c = i / 400, r = i - c * 400;
            int iy = r / 20 - 2, ix = r - (r / 20) * 20 - 2;
            float v = 0.f;
            if (iy >= 0 && iy < 16 && ix >= 0 && ix < 16)
                v = in[((b * CIN) + c0 + c) * NPOS + iy * 16 + ix];
            s_in[c][r] = v;
        }
        // stage weights: CHUNK*25 rows x 32 cols
        float* s_wf = reinterpret_cast<float*>(s_w2);
        for (int i = tid; i < CHUNK * 25 * 32; i += 128) {
            int row = i >> 5, j = i & 31;
            s_wf[i] = Wt[(c0 * 25 + row) * 512 + gch0 + j];
        }
        __syncthreads();

        for (int c = 0; c < CHUNK; c++) {
#pragma unroll
            for (int ky = 0; ky < 5; ky++) {
                const float* rin0 = &s_in[c][(y0 + ky) * 20 + x0c];
                const float* rin1 = rin0 + 160;   // +8 rows
#pragma unroll
                for (int kx = 0; kx < 5; kx++) {
                    ull vv0 = pack2(rin0[kx]);
                    ull vv1 = pack2(rin1[kx]);
                    const ull* wp = &s_w2[(c * 25 + ky * 5 + kx) * 16];
#pragma unroll
                    for (int j = 0; j < 16; j++) {
                        ull w = wp[j];
                        acc0[j] = fma2(vv0, w, acc0[j]);
                        acc1[j] = fma2(vv1, w, acc1[j]);
                    }
                }
            }
        }
        __syncthreads();
    }

    float* outb = gout + (size_t)b * 512 * NPOS;
#pragma unroll
    for (int j = 0; j < 16; j++) {
        outb[(gch0 + 2 * j)     * NPOS + p0]       = lo32(acc0[j]);
        outb[(gch0 + 2 * j + 1) * NPOS + p0]       = hi32(acc0[j]);
        outb[(gch0 + 2 * j)     * NPOS + p0 + 128] = lo32(acc1[j]);
        outb[(gch0 + 2 * j + 1) * NPOS + p0 + 128] = hi32(acc1[j]);
    }
}

// ---------------- pointwise LSTM ----------------
__global__ void lstm_pw(const float* __restrict__ gx, const float* __restrict__ gh,
                        const float* __restrict__ c_prev,
                        float* __restrict__ c_new, float* __restrict__ h_new)
{
    int idx = blockIdx.x * 256 + threadIdx.x;       // b(4b) hc(7b) pos(8b)
    if (idx >= BB * NH * NPOS) return;
    int pos = idx & 255;
    int hc  = (idx >> 8) & 127;
    int b   = idx >> 15;
    int base = (b * 512 + hc * 4) * NPOS + pos;
    float ig = gx[base]            + gh[base];
    float fg = gx[base + NPOS]     + gh[base + NPOS];
    float gg = gx[base + 2 * NPOS] + gh[base + 2 * NPOS];
    float og = gx[base + 3 * NPOS] + gh[base + 3 * NPOS];
    float c  = sigmoidf_(fg + 1.0f) * c_prev[idx] + sigmoidf_(ig) * tanhf(gg);
    c_new[idx] = c;
    h_new[idx] = sigmoidf_(og) * tanhf(c);
}

// ---------------- 1x1 projection + output store ----------------
__global__ void xgen_k(const float* __restrict__ h3, const float* __restrict__ Wlast,
                       float* __restrict__ xg, float* __restrict__ out, int t)
{
    __shared__ float s_w[FC * NH];
    int b = blockIdx.x, pos = threadIdx.x;
    for (int i = pos; i < FC * NH; i += 256) s_w[i] = Wlast[i];
    __syncthreads();
    float acc[FC];
#pragma unroll
    for (int f = 0; f < FC; f++) acc[f] = 0.f;
    for (int ch = 0; ch < NH; ch++) {
        float hv = h3[(b * NH + ch) * NPOS + pos];
#pragma unroll
        for (int f = 0; f < FC; f++) acc[f] += hv * s_w[f * NH + ch];
    }
    int y = pos >> 4, x = pos & 15;
#pragma unroll
    for (int f = 0; f < FC; f++) {
        xg[(b * FC + f) * NPOS + pos] = acc[f];
        out[((((size_t)b * NSTEP + t) * HP + y) * WP + x) * FC + f] = acc[f];
    }
}

// ---------------- masked input ----------------
__global__ void mask_k(const float* __restrict__ frames, const float* __restrict__ mask,
                       const float* __restrict__ xg, float* __restrict__ x0, int t)
{
    int idx = blockIdx.x * 256 + threadIdx.x;       // b(4) c(4) pos(8)
    if (idx >= BB * FC * NPOS) return;
    int pos = idx & 255;
    int c = (idx >> 8) & 15;
    int b = idx >> 12;
    int y = pos >> 4, x = pos & 15;
    float f = frames[((((size_t)b * TT + t) * HP + y) * WP + x) * FC + c];
    float v;
    if (t < PRE) {
        v = f;
    } else {
        float m  = mask[((((size_t)b * (NSTEP - PRE) + (t - PRE)) * HP + y) * WP + x) * FC + c];
        float xv = xg[(b * FC + c) * NPOS + pos];
        v = m * f + (1.f - m) * xv;
    }
    x0[(b * FC + c) * NPOS + pos] = v;
}

// ---------------- loss: MSE ----------------
__global__ void mse_k(const float* __restrict__ pred, const float* __restrict__ frames,
                      float* __restrict__ acc)
{
    __shared__ float s_red[256];
    float sum = 0.f;
    for (int idx = blockIdx.x * 256 + threadIdx.x; idx < OUT_FRAMES; idx += gridDim.x * 256) {
        int c = idx & 15; int r = idx >> 4;
        int x = r & 15; r >>= 4;
        int y = r & 15; r >>= 4;
        int t = r % NSTEP; int b = r / NSTEP;
        float d = pred[idx] - frames[((((size_t)b * TT + t + 1) * HP + y) * WP + x) * FC + c];
        sum += d * d;
    }
    s_red[threadIdx.x] = sum;
    __syncthreads();
    for (int s = 128; s > 0; s >>= 1) {
        if (threadIdx.x < s) s_red[threadIdx.x] += s_red[threadIdx.x + s];
        __syncthreads();
    }
    if (threadIdx.x == 0) atomicAdd(&acc[0], s_red[0]);
}

// ---------------- loss: softmax heuristic ----------------
__global__ void heur_k(const float* __restrict__ pred, const float* __restrict__ frames,
                       float* __restrict__ acc)
{
    int idx = threadIdx.x;                      // 0..303 -> (t, w)
    if (idx >= NSTEP * WP) return;
    int t = idx / WP, w = idx % WP;
    float xp = 0.f, xt = 0.f;
    for (int c = 0; c < FC; c++) {
        // pred path: softmax over b of pred[b][t][0][w][c]
        float vals[BB]; float mx = -1e30f;
        for (int b = 0; b < BB; b++) {
            vals[b] = pred[((((size_t)b * NSTEP + t) * HP + 0) * WP + w) * FC + c];
            mx = fmaxf(mx, vals[b]);
        }
        float s = 0.f, sw = 0.f;
        for (int b = 0; b < BB; b++) {
            float e = expf(vals[b] - mx);
            s += e; sw += e * (float)b;
        }
        xp += sw / s;
        // true path: frames[b][t+1][0][w][c]
        mx = -1e30f;
        for (int b = 0; b < BB; b++) {
            vals[b] = frames[((((size_t)b * TT + t + 1) * HP + 0) * WP + w) * FC + c];
            mx = fmaxf(mx, vals[b]);
        }
        s = 0.f; sw = 0.f;
        for (int b = 0; b < BB; b++) {
            float e = expf(vals[b] - mx);
            s += e; sw += e * (float)b;
        }
        xt += sw / s;
    }
    xp *= (1.f / FC); xt *= (1.f / FC);
    float d = xp - xt;
    atomicAdd(&acc[1], d * d);
}

__global__ void finalize_k(const float* __restrict__ acc, float* __restrict__ out_loss)
{
    out_loss[0] = acc[0] / (float)OUT_FRAMES + acc[1] / (float)(NSTEP * WP);
}

// ---------------- host orchestration ----------------
extern "C" void kernel_launch(void* const* d_in, const int* in_sizes, int n_in,
                              void* d_out, int out_size)
{
    const float* frames = (const float*)d_in[0];
    const float* maskp  = (const float*)d_in[1];
    const float* Wx[4]  = { (const float*)d_in[2], (const float*)d_in[4],
                            (const float*)d_in[6], (const float*)d_in[8] };
    const float* Wh[4]  = { (const float*)d_in[3], (const float*)d_in[5],
                            (const float*)d_in[7], (const float*)d_in[9] };
    const float* Wlast  = (const float*)d_in[10];
    float* out = (float*)d_out;

    void* p;
    cudaGetSymbolAddress(&p, g_h);    float* hbuf  = (float*)p;
    cudaGetSymbolAddress(&p, g_c);    float* cbuf  = (float*)p;
    cudaGetSymbolAddress(&p, g_x0);   float* x0b   = (float*)p;
    cudaGetSymbolAddress(&p, g_xg);   float* xgb   = (float*)p;
    cudaGetSymbolAddress(&p, g_gx);   float* gxb   = (float*)p;
    cudaGetSymbolAddress(&p, g_gh);   float* ghb   = (float*)p;
    cudaGetSymbolAddress(&p, g_WxT0); float* wxt0  = (float*)p;
    cudaGetSymbolAddress(&p, g_WxT);  float* wxt   = (float*)p;
    cudaGetSymbolAddress(&p, g_WhT);  float* wht   = (float*)p;
    cudaGetSymbolAddress(&p, g_acc);  float* accb  = (float*)p;

    const int LSZ = BB * NH * NPOS;            // per-layer h/c size
    const int LAYSTRIDE = NH * 25 * 512;

    // zero initial state (ping buffer 0) and loss accumulators
    zero_k<<<(LAYERS * LSZ + 255) / 256, 256>>>(hbuf, LAYERS * LSZ);
    zero_k<<<(LAYERS * LSZ + 255) / 256, 256>>>(cbuf, LAYERS * LSZ);
    zero_k<<<1, 32>>>(accb, 2);

    // transpose weights
    transpose_w<<<(512 * FC * 25 + 255) / 256, 256>>>(Wx[0], wxt0, FC);
    for (int l = 1; l < LAYERS; l++)
        transpose_w<<<(512 * NH * 25 + 255) / 256, 256>>>(Wx[l], wxt + (l - 1) * LAYSTRIDE, NH);
    for (int l = 0; l < LAYERS; l++)
        transpose_w<<<(512 * NH * 25 + 255) / 256, 256>>>(Wh[l], wht + l * LAYSTRIDE, NH);

    dim3 cgrid(16, BB);
    for (int t = 0; t < NSTEP; t++) {
        int r = t & 1, w = 1 - r;
        float* h_r = hbuf + (size_t)r * LAYERS * LSZ;
        float* h_w = hbuf + (size_t)w * LAYERS * LSZ;
        float* c_r = cbuf + (size_t)r * LAYERS * LSZ;
        float* c_w = cbuf + (size_t)w * LAYERS * LSZ;

        mask_k<<<(BB * FC * NPOS + 255) / 256, 256>>>(frames, maskp, xgb, x0b, t);

        for (int l = 0; l < LAYERS; l++) {
            const float* xin = (l == 0) ? x0b : (h_w + (size_t)(l - 1) * LSZ);
            if (l == 0)
                conv_gates<FC><<<cgrid, 128>>>(xin, wxt0, gxb);
            else
                conv_gates<NH><<<cgrid, 128>>>(xin, wxt + (l - 1) * LAYSTRIDE, gxb);
            conv_gates<NH><<<cgrid, 128>>>(h_r + (size_t)l * LSZ, wht + l * LAYSTRIDE, ghb);
            lstm_pw<<<(BB * NH * NPOS + 255) / 256, 256>>>(
                gxb, ghb, c_r + (size_t)l * LSZ,
                c_w + (size_t)l * LSZ, h_w + (size_t)l * LSZ);
        }
        xgen_k<<<BB, 256>>>(h_w + (size_t)3 * LSZ, Wlast, xgb, out, t);
    }

    mse_k<<<1024, 256>>>(out, frames, accb);
    heur_k<<<1, NSTEP * WP>>>(out, frames, accb);
    finalize_k<<<1, 1>>>(accb, out + (out_size - 1));
}

// round 4
// speedup vs baseline: 3.5303x; 3.5173x over previous
#include <cuda_runtime.h>
#include <cuda_bf16.h>
#include <math.h>
#include <stdint.h>

#define LAYERS 4
#define NH     128
#define FC     16
#define BB     16
#define TT     20
#define PRE    10
#define NPOS   256
#define NSTEP  19
#define OUT_FRAMES (BB*NSTEP*NPOS*FC)
#define HL     (BB*NPOS*NH)

#define NCH_L0   57
#define NCH_LN   100
#define BP_L0_U4 (4*NCH_L0*2048)     // 466944
#define BP_LN_U4 (4*NCH_LN*2048)     // 819200
#define TERMSZ   34560               // 240 rows * 144B max stride
#define SMEMSZ   (2*TERMSZ)          // 69120

// ---------------- device scratch ----------------
__device__ __nv_bfloat16 g_hhi[2][LAYERS][HL];
__device__ __nv_bfloat16 g_hlo[2][LAYERS][HL];
__device__ float         g_c[2][LAYERS][HL];
__device__ __nv_bfloat16 g_x0hi[BB*NPOS*FC];
__device__ __nv_bfloat16 g_x0lo[BB*NPOS*FC];
__device__ float         g_xg[BB*NPOS*FC];
__device__ uint4         g_Bp[BP_L0_U4 + 3*BP_LN_U4];   // ~46.8MB
__device__ float         g_acc[2];

__device__ __forceinline__ float sigf(float x) { return 1.f / (1.f + expf(-x)); }
__device__ __forceinline__ uint32_t smem_to_u32(const void* p) {
    uint32_t a;
    asm("{ .reg .u64 t; cvta.to.shared.u64 t, %1; cvt.u32.u64 %0, t; }" : "=r"(a) : "l"(p));
    return a;
}
__device__ __forceinline__ void ldsm4(uint32_t (&r)[4], uint32_t a) {
    asm volatile("ldmatrix.sync.aligned.m8n8.x4.shared.b16 {%0,%1,%2,%3}, [%4];"
        : "=r"(r[0]), "=r"(r[1]), "=r"(r[2]), "=r"(r[3]) : "r"(a));
}
__device__ __forceinline__ void mma16816(float (&d)[4], const uint32_t (&a)[4],
                                         uint32_t b0, uint32_t b1) {
    asm volatile("mma.sync.aligned.m16n8k16.row.col.f32.bf16.bf16.f32 "
        "{%0,%1,%2,%3}, {%4,%5,%6,%7}, {%8,%9}, {%0,%1,%2,%3};"
        : "+f"(d[0]), "+f"(d[1]), "+f"(d[2]), "+f"(d[3])
        : "r"(a[0]), "r"(a[1]), "r"(a[2]), "r"(a[3]), "r"(b0), "r"(b1));
}

__global__ void zero_k(float* p, int n) {
    int i = blockIdx.x * blockDim.x + threadIdx.x;
    if (i < n) p[i] = 0.f;
}

// ---------------- weight prepack into mma.sync B-fragment layout ----------------
// uint4 index: lane(5b) | kp(1b) | n8t(4b) | term(1b) | kc*  | ntile
// reg j of quad: kstep = kp*2 + (j>>1), k8 = j&1:
//   k_in_chunk = kstep*16 + k8*8 + (lane&3)*2 + h ;  n = n8t*8 + lane/4
__global__ void prepack_k(const float* __restrict__ Wx, const float* __restrict__ Wh,
                          uint4* __restrict__ out, int NCH, int isL0)
{
    int idx = blockIdx.x * 256 + threadIdx.x;
    if (idx >= 4 * NCH * 2048) return;
    int lane = idx & 31;
    int kp   = (idx >> 5) & 1;
    int n8t  = (idx >> 6) & 15;
    int term = (idx >> 10) & 1;
    int rest = idx >> 11;
    int kc   = rest % NCH;
    int ntile = rest / NCH;
    int nglob = ntile * 128 + n8t * 8 + (lane >> 2);
    int hc = nglob >> 2, g = nglob & 3;

    uint32_t q[4];
#pragma unroll
    for (int j = 0; j < 4; j++) {
        uint32_t rr = 0;
#pragma unroll
        for (int h = 0; h < 2; h++) {
            int klocal = (kp * 2 + (j >> 1)) * 16 + (j & 1) * 8 + (lane & 3) * 2 + h;
            float w;
            if (isL0) {
                if (kc < 7) {
                    int ks = klocal >> 4, kk = klocal & 15;
                    int tap = kc * 4 + ks;
                    w = (tap <= 24) ? Wx[((g * 128 + hc) * 16 + kk) * 25 + tap] : 0.f;
                } else {
                    int j2 = kc - 7, seg = j2 / 25, tap = j2 % 25;
                    int c = seg * 64 + klocal;
                    w = Wh[((g * 128 + hc) * 128 + c) * 25 + tap];
                }
            } else {
                int seg = kc / 25, tap = kc % 25;
                int c = (seg & 1) * 64 + klocal;
                const float* src = (seg < 2) ? Wx : Wh;
                w = src[((g * 128 + hc) * 128 + c) * 25 + tap];
            }
            __nv_bfloat16 hi = __float2bfloat16(w);
            __nv_bfloat16 v = term ? __float2bfloat16(w - __bfloat162float(hi)) : hi;
            rr |= (uint32_t)__bfloat16_as_ushort(v) << (16 * h);
        }
        q[j] = rr;
    }
    out[idx] = make_uint4(q[0], q[1], q[2], q[3]);
}

// ---------------- fused mma.sync GEMM + LSTM pointwise ----------------
// grid (4 ntiles, 32 mtiles), 256 thr (8 warps: wm = wid&1 (64m), wn = wid>>1 (32n)).
// CTA tile 128m x 128n. K ordered tap-innermost per channel-block; A = shifted
// reads of a once-staged padded raw image (240 rows). B prepacked frag-direct.
template<bool L0>
__global__ void __launch_bounds__(256) gemm_lstm(
    const __nv_bfloat16* __restrict__ xhi, const __nv_bfloat16* __restrict__ xlo,
    const __nv_bfloat16* __restrict__ hhi, const __nv_bfloat16* __restrict__ hlo,
    const uint4* __restrict__ Bp,
    const float* __restrict__ cprev, float* __restrict__ cnew,
    __nv_bfloat16* __restrict__ hhiout, __nv_bfloat16* __restrict__ hloout)
{
    constexpr int NCH = L0 ? NCH_L0 : NCH_LN;
    extern __shared__ __align__(128) char smem[];
    const int tid = threadIdx.x, lane = tid & 31, wid = tid >> 5;
    const int wm = wid & 1, wn = wid >> 1;
    const int ntile = blockIdx.x, mt2 = blockIdx.y;
    const int b = mt2 >> 1, pos0 = (mt2 & 1) << 7, yb0 = (mt2 & 1) << 3;
    const uint32_t sA = smem_to_u32(smem);
    const int half16 = (lane >> 4) * 16;

    int ylocal[4], xcol[4];
#pragma unroll
    for (int mt = 0; mt < 4; mt++) {
        int pos = pos0 + wm * 64 + mt * 16 + (lane & 15);
        ylocal[mt] = (pos >> 4) - yb0;
        xcol[mt] = pos & 15;
    }

    float acc[4][4][4];
#pragma unroll
    for (int a = 0; a < 4; a++)
#pragma unroll
        for (int c = 0; c < 4; c++)
#pragma unroll
            for (int d = 0; d < 4; d++) acc[a][c][d] = 0.f;

    // stage padded raw image: 240 rows (12 y x 20 x), 2 terms
    auto stage = [&](const __nv_bfloat16* shi, const __nv_bfloat16* slo,
                     int CIN, int coff, int nu4, int stride) {
        __syncthreads();
        for (int job = tid; job < 480; job += 256) {
            int term = job >= 240, r = job - term * 240;
            int yy = yb0 - 2 + r / 20, xx = r % 20 - 2;
            uint4* dst = (uint4*)(smem + term * TERMSZ + r * stride);
            if (yy >= 0 && yy < 16 && xx >= 0 && xx < 16) {
                const uint4* sp = (const uint4*)((term ? slo : shi) +
                    (size_t)(((b << 8) + (yy << 4) + xx)) * CIN + coff);
                for (int j = 0; j < nu4; j++) dst[j] = sp[j];
            } else {
                uint4 z = make_uint4(0, 0, 0, 0);
                for (int j = 0; j < nu4; j++) dst[j] = z;
            }
        }
        __syncthreads();
    };

    for (int kc = 0; kc < NCH; kc++) {
        int tap = 0, strideA;
        bool xseg = false;
        if (L0) {
            if (kc < 7) {
                xseg = true; strideA = 48;
                if (kc == 0) stage(xhi, xlo, 16, 0, 2, 48);
            } else {
                int j = kc - 7, seg = j / 25; tap = j % 25; strideA = 144;
                if (tap == 0) stage(hhi, hlo, 128, seg * 64, 8, 144);
            }
        } else {
            int seg = kc / 25; tap = kc % 25; strideA = 144;
            if (tap == 0) {
                const __nv_bfloat16* sh = (seg < 2) ? xhi : hhi;
                const __nv_bfloat16* sl = (seg < 2) ? xlo : hlo;
                stage(sh, sl, 128, (seg & 1) * 64, 8, 144);
            }
        }

        // B fragments for this chunk (straight to registers)
        const uint4* bc = Bp + ((size_t)(ntile * NCH + kc) * 2048);
        uint4 Breg[2][4][2];
#pragma unroll
        for (int t2 = 0; t2 < 2; t2++)
#pragma unroll
            for (int nt = 0; nt < 4; nt++)
#pragma unroll
                for (int kp = 0; kp < 2; kp++)
                    Breg[t2][nt][kp] = bc[t2 * 1024 + (wn * 4 + nt) * 64 + kp * 32 + lane];

#pragma unroll
        for (int ks = 0; ks < 4; ks++) {
            int tapk, kb;
            if (L0 && xseg) {
                tapk = kc * 4 + ks; if (tapk > 24) tapk = 24;
                kb = 0;
            } else {
                tapk = tap; kb = ks * 32;
            }
            int ky = tapk / 5, kx = tapk - ky * 5;
            uint32_t Ah[4][4], Al[4][4];
#pragma unroll
            for (int mt = 0; mt < 4; mt++) {
                uint32_t row = (uint32_t)((ylocal[mt] + ky) * 20 + xcol[mt] + kx);
                uint32_t ad = sA + row * strideA + half16 + kb;
                ldsm4(Ah[mt], ad);
                ldsm4(Al[mt], ad + TERMSZ);
            }
#pragma unroll
            for (int mt = 0; mt < 4; mt++) {
#pragma unroll
                for (int nt = 0; nt < 4; nt++) {
                    uint4 bh4 = Breg[0][nt][ks >> 1];
                    uint4 bl4 = Breg[1][nt][ks >> 1];
                    uint32_t bh0 = (ks & 1) ? bh4.z : bh4.x;
                    uint32_t bh1 = (ks & 1) ? bh4.w : bh4.y;
                    uint32_t bl0 = (ks & 1) ? bl4.z : bl4.x;
                    uint32_t bl1 = (ks & 1) ? bl4.w : bl4.y;
                    mma16816(acc[mt][nt], Ah[mt], bh0, bh1);
                    mma16816(acc[mt][nt], Ah[mt], bl0, bl1);
                    mma16816(acc[mt][nt], Al[mt], bh0, bh1);
                }
            }
        }
    }

    // ---- LSTM pointwise epilogue ----
    const int role = lane & 1;
#pragma unroll
    for (int mt = 0; mt < 4; mt++) {
#pragma unroll
        for (int nt = 0; nt < 4; nt++) {
            float* a = acc[mt][nt];
            float s0 = role ? a[0] : a[2];
            float s1 = role ? a[1] : a[3];
            float r0 = __shfl_xor_sync(0xffffffffu, s0, 1);
            float r1 = __shfl_xor_sync(0xffffffffu, s1, 1);
            float gi, gf, gg, go;
            int mrow;
            if (role == 0) { gi = a[0]; gf = a[1]; gg = r0; go = r1; mrow = lane >> 2; }
            else           { gi = r0;  gf = r1;  gg = a[2]; go = a[3]; mrow = (lane >> 2) + 8; }
            int pos = pos0 + wm * 64 + mt * 16 + mrow;
            int hc = ntile * 32 + wn * 8 + nt * 2 + ((lane & 3) >> 1);
            size_t ci = ((size_t)((b << 8) + pos) << 7) + hc;
            float cv = sigf(gf + 1.0f) * cprev[ci] + sigf(gi) * tanhf(gg);
            cnew[ci] = cv;
            float hv = sigf(go) * tanhf(cv);
            __nv_bfloat16 hh = __float2bfloat16(hv);
            hhiout[ci] = hh;
            hloout[ci] = __float2bfloat16(hv - __bfloat162float(hh));
        }
    }
}

// ---------------- 1x1 projection ----------------
__global__ void xgen_k(const __nv_bfloat16* __restrict__ hhi3, const __nv_bfloat16* __restrict__ hlo3,
                       const float* __restrict__ Wlast,
                       float* __restrict__ xg, float* __restrict__ out, int t)
{
    __shared__ float s_w[FC * NH];
    int b = blockIdx.x, pos = threadIdx.x;
    for (int i = pos; i < FC * NH; i += 256) s_w[i] = Wlast[i];
    __syncthreads();
    size_t hb = ((size_t)(b * 256 + pos)) << 7;
    float acc[FC];
#pragma unroll
    for (int f = 0; f < FC; f++) acc[f] = 0.f;
    for (int ch = 0; ch < NH; ch++) {
        float hv = __bfloat162float(hhi3[hb + ch]) + __bfloat162float(hlo3[hb + ch]);
#pragma unroll
        for (int f = 0; f < FC; f++) acc[f] += hv * s_w[f * NH + ch];
    }
    size_t ob = ((size_t)(b * NSTEP + t) * 256 + pos) * 16;
    size_t xb = ((size_t)(b * 256 + pos)) * 16;
#pragma unroll
    for (int f = 0; f < FC; f++) { xg[xb + f] = acc[f]; out[ob + f] = acc[f]; }
}

// ---------------- masked input + bf16 split ----------------
__global__ void mask_k(const float* __restrict__ frames, const float* __restrict__ mask,
                       const float* __restrict__ xg,
                       __nv_bfloat16* __restrict__ x0hi, __nv_bfloat16* __restrict__ x0lo, int t)
{
    int idx = blockIdx.x * 256 + threadIdx.x;
    if (idx >= BB * NPOS * FC) return;
    int c = idx & 15, pos = (idx >> 4) & 255, b = idx >> 12;
    float f = frames[(((size_t)(b * TT + t)) * 256 + pos) * 16 + c];
    float v;
    if (t < PRE) v = f;
    else {
        float mm = mask[(((size_t)(b * (NSTEP - PRE) + (t - PRE))) * 256 + pos) * 16 + c];
        v = mm * f + (1.f - mm) * xg[idx];
    }
    __nv_bfloat16 hi = __float2bfloat16(v);
    x0hi[idx] = hi;
    x0lo[idx] = __float2bfloat16(v - __bfloat162float(hi));
}

// ---------------- losses ----------------
__global__ void mse_k(const float* __restrict__ pred, const float* __restrict__ frames,
                      float* __restrict__ acc)
{
    __shared__ float s_red[256];
    float sum = 0.f;
    for (int idx = blockIdx.x * 256 + threadIdx.x; idx < OUT_FRAMES; idx += gridDim.x * 256) {
        int c = idx & 15, pos = (idx >> 4) & 255, r = idx >> 12;
        int t = r % NSTEP, b = r / NSTEP;
        float d = pred[idx] - frames[(((size_t)(b * TT + t + 1)) * 256 + pos) * 16 + c];
        sum += d * d;
    }
    s_red[threadIdx.x] = sum;
    __syncthreads();
    for (int s = 128; s > 0; s >>= 1) {
        if (threadIdx.x < s) s_red[threadIdx.x] += s_red[threadIdx.x + s];
        __syncthreads();
    }
    if (threadIdx.x == 0) atomicAdd(&acc[0], s_red[0]);
}

__global__ void heur_k(const float* __restrict__ pred, const float* __restrict__ frames,
                       float* __restrict__ acc)
{
    int idx = threadIdx.x;
    if (idx >= NSTEP * 16) return;
    int t = idx / 16, w = idx % 16;
    float xp = 0.f, xt = 0.f;
    for (int c = 0; c < FC; c++) {
        float vals[BB]; float mx = -1e30f;
        for (int b = 0; b < BB; b++) {
            vals[b] = pred[(((size_t)(b * NSTEP + t)) * 256 + w) * 16 + c];
            mx = fmaxf(mx, vals[b]);
        }
        float s = 0.f, sw = 0.f;
        for (int b = 0; b < BB; b++) { float e = expf(vals[b] - mx); s += e; sw += e * (float)b; }
        xp += sw / s;
        mx = -1e30f;
        for (int b = 0; b < BB; b++) {
            vals[b] = frames[(((size_t)(b * TT + t + 1)) * 256 + w) * 16 + c];
            mx = fmaxf(mx, vals[b]);
        }
        s = 0.f; sw = 0.f;
        for (int b = 0; b < BB; b++) { float e = expf(vals[b] - mx); s += e; sw += e * (float)b; }
        xt += sw / s;
    }
    xp *= (1.f / FC); xt *= (1.f / FC);
    float d = xp - xt;
    atomicAdd(&acc[1], d * d);
}

__global__ void finalize_k(const float* __restrict__ acc, float* __restrict__ out_loss)
{
    out_loss[0] = acc[0] / (float)OUT_FRAMES + acc[1] / (float)(NSTEP * 16);
}

// ---------------- host orchestration ----------------
extern "C" void kernel_launch(void* const* d_in, const int* in_sizes, int n_in,
                              void* d_out, int out_size)
{
    const float* frames = (const float*)d_in[0];
    const float* maskp  = (const float*)d_in[1];
    const float* Wx[4]  = { (const float*)d_in[2], (const float*)d_in[4],
                            (const float*)d_in[6], (const float*)d_in[8] };
    const float* Wh[4]  = { (const float*)d_in[3], (const float*)d_in[5],
                            (const float*)d_in[7], (const float*)d_in[9] };
    const float* Wlast  = (const float*)d_in[10];
    float* out = (float*)d_out;

    void* p;
    cudaGetSymbolAddress(&p, g_hhi);  __nv_bfloat16* hhi = (__nv_bfloat16*)p;
    cudaGetSymbolAddress(&p, g_hlo);  __nv_bfloat16* hlo = (__nv_bfloat16*)p;
    cudaGetSymbolAddress(&p, g_c);    float* cbuf = (float*)p;
    cudaGetSymbolAddress(&p, g_x0hi); __nv_bfloat16* x0hi = (__nv_bfloat16*)p;
    cudaGetSymbolAddress(&p, g_x0lo); __nv_bfloat16* x0lo = (__nv_bfloat16*)p;
    cudaGetSymbolAddress(&p, g_xg);   float* xgb = (float*)p;
    cudaGetSymbolAddress(&p, g_Bp);   uint4* bp = (uint4*)p;
    cudaGetSymbolAddress(&p, g_acc);  float* accb = (float*)p;

    cudaFuncSetAttribute(gemm_lstm<true>,  cudaFuncAttributeMaxDynamicSharedMemorySize, SMEMSZ);
    cudaFuncSetAttribute(gemm_lstm<false>, cudaFuncAttributeMaxDynamicSharedMemorySize, SMEMSZ);

    // zero initial state (ping 0) and accumulators
    zero_k<<<(LAYERS * HL / 2 + 255) / 256, 256>>>((float*)hhi, LAYERS * HL / 2);
    zero_k<<<(LAYERS * HL / 2 + 255) / 256, 256>>>((float*)hlo, LAYERS * HL / 2);
    zero_k<<<(LAYERS * HL + 255) / 256, 256>>>(cbuf, LAYERS * HL);
    zero_k<<<1, 32>>>(accb, 2);

    // prepack weights into B-fragment layout
    prepack_k<<<BP_L0_U4 / 256, 256>>>(Wx[0], Wh[0], bp, NCH_L0, 1);
    for (int l = 1; l < LAYERS; l++)
        prepack_k<<<BP_LN_U4 / 256, 256>>>(Wx[l], Wh[l],
            bp + BP_L0_U4 + (size_t)(l - 1) * BP_LN_U4, NCH_LN, 0);

    dim3 ggrid(4, 32);
    for (int t = 0; t < NSTEP; t++) {
        int r = t & 1, w = 1 - r;
        __nv_bfloat16* hhr = hhi + (size_t)r * LAYERS * HL;
        __nv_bfloat16* hhw = hhi + (size_t)w * LAYERS * HL;
        __nv_bfloat16* hlr = hlo + (size_t)r * LAYERS * HL;
        __nv_bfloat16* hlw = hlo + (size_t)w * LAYERS * HL;
        float* cr = cbuf + (size_t)r * LAYERS * HL;
        float* cw = cbuf + (size_t)w * LAYERS * HL;

        mask_k<<<(BB * NPOS * FC + 255) / 256, 256>>>(frames, maskp, xgb, x0hi, x0lo, t);

        gemm_lstm<true><<<ggrid, 256, SMEMSZ>>>(
            x0hi, x0lo, hhr, hlr, bp, cr, cw, hhw, hlw);
        for (int l = 1; l < LAYERS; l++) {
            gemm_lstm<false><<<ggrid, 256, SMEMSZ>>>(
                hhw + (size_t)(l - 1) * HL, hlw + (size_t)(l - 1) * HL,
                hhr + (size_t)l * HL,       hlr + (size_t)l * HL,
                bp + BP_L0_U4 + (size_t)(l - 1) * BP_LN_U4,
                cr + (size_t)l * HL, cw + (size_t)l * HL,
                hhw + (size_t)l * HL, hlw + (size_t)l * HL);
        }
        xgen_k<<<BB, 256>>>(hhw + (size_t)3 * HL, hlw + (size_t)3 * HL, Wlast, xgb, out, t);
    }

    mse_k<<<1024, 256>>>(out, frames, accb);
    heur_k<<<1, NSTEP * 16>>>(out, frames, accb);
    finalize_k<<<1, 1>>>(accb, out + (out_size - 1));
}

// round 5
// speedup vs baseline: 3.6282x; 1.0277x over previous
#include <cuda_runtime.h>
#include <cuda_fp16.h>
#include <math.h>
#include <stdint.h>

#define LAYERS 4
#define NH     128
#define FC     16
#define BB     16
#define TT     20
#define PRE    10
#define NPOS   256
#define NSTEP  19
#define OUT_FRAMES (BB*NSTEP*NPOS*FC)
#define HL     (BB*NPOS*NH)

#define NCH_L0   57
#define NCH_LN   100
#define BP_L0_U4 (4*NCH_L0*2048)     // 466944
#define BP_LN_U4 (4*NCH_LN*2048)     // 819200
#define BP_TOTAL (BP_L0_U4 + 3*BP_LN_U4)
#define TERMSZ   34560               // 240 rows * 144B max stride
#define SMEMSZ   (2*TERMSZ)
#define LOSCALE  2048.0f
#define INVLO    (1.0f/2048.0f)

// ---------------- device scratch ----------------
__device__ __half  g_hhi[2][LAYERS][HL];
__device__ __half  g_hlo[2][LAYERS][HL];
__device__ float   g_c[2][LAYERS][HL];
__device__ __half  g_x0hi[BB*NPOS*FC];
__device__ __half  g_x0lo[BB*NPOS*FC];
__device__ float   g_xg[BB*NPOS*FC];
__device__ uint4   g_Bp[BP_TOTAL];
__device__ float   g_acc[2];

__device__ __forceinline__ float sigf(float x) { return 1.f / (1.f + expf(-x)); }
__device__ __forceinline__ uint32_t smem_to_u32(const void* p) {
    uint32_t a;
    asm("{ .reg .u64 t; cvta.to.shared.u64 t, %1; cvt.u32.u64 %0, t; }" : "=r"(a) : "l"(p));
    return a;
}
__device__ __forceinline__ void ldsm4(uint32_t (&r)[4], uint32_t a) {
    asm volatile("ldmatrix.sync.aligned.m8n8.x4.shared.b16 {%0,%1,%2,%3}, [%4];"
        : "=r"(r[0]), "=r"(r[1]), "=r"(r[2]), "=r"(r[3]) : "r"(a));
}
__device__ __forceinline__ void mma_f32(float (&d)[4], const uint32_t (&a)[4],
                                        uint32_t b0, uint32_t b1) {
    asm volatile("mma.sync.aligned.m16n8k16.row.col.f32.f16.f16.f32 "
        "{%0,%1,%2,%3}, {%4,%5,%6,%7}, {%8,%9}, {%0,%1,%2,%3};"
        : "+f"(d[0]), "+f"(d[1]), "+f"(d[2]), "+f"(d[3])
        : "r"(a[0]), "r"(a[1]), "r"(a[2]), "r"(a[3]), "r"(b0), "r"(b1));
}
__device__ __forceinline__ void mma_f16(uint32_t (&c)[2], const uint32_t (&a)[4],
                                        uint32_t b0, uint32_t b1) {
    asm volatile("mma.sync.aligned.m16n8k16.row.col.f16.f16.f16.f16 "
        "{%0,%1}, {%2,%3,%4,%5}, {%6,%7}, {%0,%1};"
        : "+r"(c[0]), "+r"(c[1])
        : "r"(a[0]), "r"(a[1]), "r"(a[2]), "r"(a[3]), "r"(b0), "r"(b1));
}

// ---------------- fused zero init (1 launch) ----------------
__global__ void zero_all(__half* h1, __half* h2, float* c, float* acc)
{
    int i = blockIdx.x * 256 + threadIdx.x;
    const int NH2 = LAYERS * HL / 2;       // hhi ping0 as float count
    if (i < NH2) ((float*)h1)[i] = 0.f;
    if (i < NH2) ((float*)h2)[i] = 0.f;
    if (i < LAYERS * HL) c[i] = 0.f;
    if (i < 2) acc[i] = 0.f;
}

// ---------------- weight prepack, all layers, 1 launch ----------------
__global__ void prepack_all(const float* __restrict__ Wx0, const float* __restrict__ Wh0,
                            const float* __restrict__ Wx1, const float* __restrict__ Wh1,
                            const float* __restrict__ Wx2, const float* __restrict__ Wh2,
                            const float* __restrict__ Wx3, const float* __restrict__ Wh3,
                            uint4* __restrict__ outb)
{
    int gidx = blockIdx.x * 256 + threadIdx.x;
    if (gidx >= BP_TOTAL) return;
    const float* Wx; const float* Wh; int NCH, isL0, idx;
    if (gidx < BP_L0_U4) { Wx = Wx0; Wh = Wh0; NCH = NCH_L0; isL0 = 1; idx = gidx; }
    else {
        int r = gidx - BP_L0_U4, l = r / BP_LN_U4;
        idx = r - l * BP_LN_U4; NCH = NCH_LN; isL0 = 0;
        Wx = (l == 0) ? Wx1 : (l == 1) ? Wx2 : Wx3;
        Wh = (l == 0) ? Wh1 : (l == 1) ? Wh2 : Wh3;
    }
    int lane = idx & 31;
    int kp   = (idx >> 5) & 1;
    int n8t  = (idx >> 6) & 15;
    int term = (idx >> 10) & 1;
    int rest = idx >> 11;
    int kc   = rest % NCH;
    int ntile = rest / NCH;
    int nglob = ntile * 128 + n8t * 8 + (lane >> 2);
    int hc = nglob >> 2, g = nglob & 3;

    uint32_t q[4];
#pragma unroll
    for (int j = 0; j < 4; j++) {
        uint32_t rr = 0;
#pragma unroll
        for (int h = 0; h < 2; h++) {
            int klocal = (kp * 2 + (j >> 1)) * 16 + (j & 1) * 8 + (lane & 3) * 2 + h;
            float w;
            if (isL0) {
                if (kc < 7) {
                    int ks = klocal >> 4, kk = klocal & 15;
                    int tap = kc * 4 + ks;
                    w = (tap <= 24) ? Wx[((g * 128 + hc) * 16 + kk) * 25 + tap] : 0.f;
                } else {
                    int j2 = kc - 7, seg = j2 / 25, tap = j2 % 25;
                    int c = seg * 64 + klocal;
                    w = Wh[((g * 128 + hc) * 128 + c) * 25 + tap];
                }
            } else {
                int seg = kc / 25, tap = kc % 25;
                int c = (seg & 1) * 64 + klocal;
                const float* src = (seg < 2) ? Wx : Wh;
                w = src[((g * 128 + hc) * 128 + c) * 25 + tap];
            }
            __half hi = __float2half(w);
            __half v = term ? __float2half((w - __half2float(hi)) * LOSCALE) : hi;
            rr |= (uint32_t)__half_as_ushort(v) << (16 * h);
        }
        q[j] = rr;
    }
    outb[gidx] = make_uint4(q[0], q[1], q[2], q[3]);
}

// ---------------- fused mma.sync GEMM + LSTM pointwise ----------------
template<bool L0>
__global__ void __launch_bounds__(256) gemm_lstm(
    const __half* __restrict__ xhi, const __half* __restrict__ xlo,
    const __half* __restrict__ hhi, const __half* __restrict__ hlo,
    const uint4* __restrict__ Bp,
    const float* __restrict__ cprev, float* __restrict__ cnew,
    __half* __restrict__ hhiout, __half* __restrict__ hloout)
{
    constexpr int NCH = L0 ? NCH_L0 : NCH_LN;
    extern __shared__ __align__(128) char smem[];
    const int tid = threadIdx.x, lane = tid & 31, wid = tid >> 5;
    const int wm = wid & 1, wn = wid >> 1;
    const int ntile = blockIdx.x, mt2 = blockIdx.y;
    const int b = mt2 >> 1, pos0 = (mt2 & 1) << 7, yb0 = (mt2 & 1) << 3;
    const uint32_t sA = smem_to_u32(smem);
    const int half16 = (lane >> 4) * 16;

    int ylocal[4], xcol[4];
#pragma unroll
    for (int mt = 0; mt < 4; mt++) {
        int pos = pos0 + wm * 64 + mt * 16 + (lane & 15);
        ylocal[mt] = (pos >> 4) - yb0;
        xcol[mt] = pos & 15;
    }

    float acc[4][4][4];
    uint32_t acc16[4][4][2];
#pragma unroll
    for (int a = 0; a < 4; a++)
#pragma unroll
        for (int c = 0; c < 4; c++) {
#pragma unroll
            for (int d = 0; d < 4; d++) acc[a][c][d] = 0.f;
            acc16[a][c][0] = 0u; acc16[a][c][1] = 0u;
        }

    auto stage = [&](const __half* shi, const __half* slo,
                     int CIN, int coff, int nu4, int stride) {
        __syncthreads();
        for (int job = tid; job < 480; job += 256) {
            int term = job >= 240, r = job - term * 240;
            int yy = yb0 - 2 + r / 20, xx = r % 20 - 2;
            uint4* dst = (uint4*)(smem + term * TERMSZ + r * stride);
            if (yy >= 0 && yy < 16 && xx >= 0 && xx < 16) {
                const uint4* sp = (const uint4*)((term ? slo : shi) +
                    (size_t)(((b << 8) + (yy << 4) + xx)) * CIN + coff);
                for (int j = 0; j < nu4; j++) dst[j] = sp[j];
            } else {
                uint4 z = make_uint4(0, 0, 0, 0);
                for (int j = 0; j < nu4; j++) dst[j] = z;
            }
        }
        __syncthreads();
    };

    for (int kc = 0; kc < NCH; kc++) {
        int tap = 0, strideA;
        bool xseg = false;
        if (L0) {
            if (kc < 7) {
                xseg = true; strideA = 48;
                if (kc == 0) stage(xhi, xlo, 16, 0, 2, 48);
            } else {
                int j = kc - 7, seg = j / 25; tap = j % 25; strideA = 144;
                if (tap == 0) stage(hhi, hlo, 128, seg * 64, 8, 144);
            }
        } else {
            int seg = kc / 25; tap = kc % 25; strideA = 144;
            if (tap == 0) {
                const __half* sh = (seg < 2) ? xhi : hhi;
                const __half* sl = (seg < 2) ? xlo : hlo;
                stage(sh, sl, 128, (seg & 1) * 64, 8, 144);
            }
        }

        const uint4* bc = Bp + ((size_t)(ntile * NCH + kc) * 2048);
        uint4 Breg[2][4][2];
#pragma unroll
        for (int t2 = 0; t2 < 2; t2++)
#pragma unroll
            for (int nt = 0; nt < 4; nt++)
#pragma unroll
                for (int kp = 0; kp < 2; kp++)
                    Breg[t2][nt][kp] = bc[t2 * 1024 + (wn * 4 + nt) * 64 + kp * 32 + lane];

#pragma unroll
        for (int ks = 0; ks < 4; ks++) {
            int tapk, kb;
            if (L0 && xseg) {
                tapk = kc * 4 + ks; if (tapk > 24) tapk = 24;
                kb = 0;
            } else {
                tapk = tap; kb = ks * 32;
            }
            int ky = tapk / 5, kx = tapk - ky * 5;
            uint32_t Ah[4][4], Al[4][4];
#pragma unroll
            for (int mt = 0; mt < 4; mt++) {
                uint32_t row = (uint32_t)((ylocal[mt] + ky) * 20 + xcol[mt] + kx);
                uint32_t ad = sA + row * strideA + half16 + kb;
                ldsm4(Ah[mt], ad);
                ldsm4(Al[mt], ad + TERMSZ);
            }
#pragma unroll
            for (int mt = 0; mt < 4; mt++) {
#pragma unroll
                for (int nt = 0; nt < 4; nt++) {
                    uint4 bh4 = Breg[0][nt][ks >> 1];
                    uint4 bl4 = Breg[1][nt][ks >> 1];
                    uint32_t bh0 = (ks & 1) ? bh4.z : bh4.x;
                    uint32_t bh1 = (ks & 1) ? bh4.w : bh4.y;
                    uint32_t bl0 = (ks & 1) ? bl4.z : bl4.x;
                    uint32_t bl1 = (ks & 1) ? bl4.w : bl4.y;
                    mma_f32(acc[mt][nt], Ah[mt], bh0, bh1);
                    mma_f16(acc16[mt][nt], Ah[mt], bl0, bl1);
                    mma_f16(acc16[mt][nt], Al[mt], bh0, bh1);
                }
            }
        }
    }

    // ---- combine correction terms + LSTM pointwise epilogue ----
    const int role = lane & 1;
#pragma unroll
    for (int mt = 0; mt < 4; mt++) {
#pragma unroll
        for (int nt = 0; nt < 4; nt++) {
            float* a = acc[mt][nt];
            float2 c0 = __half22float2(*reinterpret_cast<__half2*>(&acc16[mt][nt][0]));
            float2 c1 = __half22float2(*reinterpret_cast<__half2*>(&acc16[mt][nt][1]));
            a[0] += c0.x * INVLO; a[1] += c0.y * INVLO;
            a[2] += c1.x * INVLO; a[3] += c1.y * INVLO;
            float s0 = role ? a[0] : a[2];
            float s1 = role ? a[1] : a[3];
            float r0 = __shfl_xor_sync(0xffffffffu, s0, 1);
            float r1 = __shfl_xor_sync(0xffffffffu, s1, 1);
            float gi, gf, gg, go;
            int mrow;
            if (role == 0) { gi = a[0]; gf = a[1]; gg = r0; go = r1; mrow = lane >> 2; }
            else           { gi = r0;  gf = r1;  gg = a[2]; go = a[3]; mrow = (lane >> 2) + 8; }
            int pos = pos0 + wm * 64 + mt * 16 + mrow;
            int hc = ntile * 32 + wn * 8 + nt * 2 + ((lane & 3) >> 1);
            size_t ci = ((size_t)((b << 8) + pos) << 7) + hc;
            float cv = sigf(gf + 1.0f) * cprev[ci] + sigf(gi) * tanhf(gg);
            cnew[ci] = cv;
            float hv = sigf(go) * tanhf(cv);
            __half hh = __float2half(hv);
            hhiout[ci] = hh;
            hloout[ci] = __float2half((hv - __half2float(hh)) * LOSCALE);
        }
    }
}

// ---------------- 1x1 projection ----------------
__global__ void xgen_k(const __half* __restrict__ hhi3, const __half* __restrict__ hlo3,
                       const float* __restrict__ Wlast,
                       float* __restrict__ xg, float* __restrict__ out, int t)
{
    __shared__ float s_w[FC * NH];
    int b = blockIdx.x, pos = threadIdx.x;
    for (int i = pos; i < FC * NH; i += 256) s_w[i] = Wlast[i];
    __syncthreads();
    size_t hb = ((size_t)(b * 256 + pos)) << 7;
    float acc[FC];
#pragma unroll
    for (int f = 0; f < FC; f++) acc[f] = 0.f;
    for (int ch = 0; ch < NH; ch++) {
        float hv = __half2float(hhi3[hb + ch]) + __half2float(hlo3[hb + ch]) * INVLO;
#pragma unroll
        for (int f = 0; f < FC; f++) acc[f] += hv * s_w[f * NH + ch];
    }
    size_t ob = ((size_t)(b * NSTEP + t) * 256 + pos) * 16;
    size_t xb = ((size_t)(b * 256 + pos)) * 16;
#pragma unroll
    for (int f = 0; f < FC; f++) { xg[xb + f] = acc[f]; out[ob + f] = acc[f]; }
}

// ---------------- masked input + fp16 split ----------------
__global__ void mask_k(const float* __restrict__ frames, const float* __restrict__ mask,
                       const float* __restrict__ xg,
                       __half* __restrict__ x0hi, __half* __restrict__ x0lo, int t)
{
    int idx = blockIdx.x * 256 + threadIdx.x;
    if (idx >= BB * NPOS * FC) return;
    int c = idx & 15, pos = (idx >> 4) & 255, b = idx >> 12;
    float f = frames[(((size_t)(b * TT + t)) * 256 + pos) * 16 + c];
    float v;
    if (t < PRE) v = f;
    else {
        float mm = mask[(((size_t)(b * (NSTEP - PRE) + (t - PRE))) * 256 + pos) * 16 + c];
        v = mm * f + (1.f - mm) * xg[idx];
    }
    __half hi = __float2half(v);
    x0hi[idx] = hi;
    x0lo[idx] = __float2half((v - __half2float(hi)) * LOSCALE);
}

// ---------------- losses ----------------
__global__ void mse_k(const float* __restrict__ pred, const float* __restrict__ frames,
                      float* __restrict__ acc)
{
    __shared__ float s_red[256];
    float sum = 0.f;
    for (int idx = blockIdx.x * 256 + threadIdx.x; idx < OUT_FRAMES; idx += gridDim.x * 256) {
        int c = idx & 15, pos = (idx >> 4) & 255, r = idx >> 12;
        int t = r % NSTEP, b = r / NSTEP;
        float d = pred[idx] - frames[(((size_t)(b * TT + t + 1)) * 256 + pos) * 16 + c];
        sum += d * d;
    }
    s_red[threadIdx.x] = sum;
    __syncthreads();
    for (int s = 128; s > 0; s >>= 1) {
        if (threadIdx.x < s) s_red[threadIdx.x] += s_red[threadIdx.x + s];
        __syncthreads();
    }
    if (threadIdx.x == 0) atomicAdd(&acc[0], s_red[0]);
}

__global__ void heur_k(const float* __restrict__ pred, const float* __restrict__ frames,
                       float* __restrict__ acc)
{
    int idx = threadIdx.x;
    if (idx >= NSTEP * 16) return;
    int t = idx / 16, w = idx % 16;
    float xp = 0.f, xt = 0.f;
    for (int c = 0; c < FC; c++) {
        float vals[BB]; float mx = -1e30f;
        for (int b = 0; b < BB; b++) {
            vals[b] = pred[(((size_t)(b * NSTEP + t)) * 256 + w) * 16 + c];
            mx = fmaxf(mx, vals[b]);
        }
        float s = 0.f, sw = 0.f;
        for (int b = 0; b < BB; b++) { float e = expf(vals[b] - mx); s += e; sw += e * (float)b; }
        xp += sw / s;
        mx = -1e30f;
        for (int b = 0; b < BB; b++) {
            vals[b] = frames[(((size_t)(b * TT + t + 1)) * 256 + w) * 16 + c];
            mx = fmaxf(mx, vals[b]);
        }
        s = 0.f; sw = 0.f;
        for (int b = 0; b < BB; b++) { float e = expf(vals[b] - mx); s += e; sw += e * (float)b; }
        xt += sw / s;
    }
    xp *= (1.f / FC); xt *= (1.f / FC);
    float d = xp - xt;
    atomicAdd(&acc[1], d * d);
}

__global__ void finalize_k(const float* __restrict__ acc, float* __restrict__ out_loss)
{
    out_loss[0] = acc[0] / (float)OUT_FRAMES + acc[1] / (float)(NSTEP * 16);
}

// ---------------- host orchestration ----------------
extern "C" void kernel_launch(void* const* d_in, const int* in_sizes, int n_in,
                              void* d_out, int out_size)
{
    const float* frames = (const float*)d_in[0];
    const float* maskp  = (const float*)d_in[1];
    const float* Wlast  = (const float*)d_in[10];
    float* out = (float*)d_out;

    void* p;
    cudaGetSymbolAddress(&p, g_hhi);  __half* hhi = (__half*)p;
    cudaGetSymbolAddress(&p, g_hlo);  __half* hlo = (__half*)p;
    cudaGetSymbolAddress(&p, g_c);    float* cbuf = (float*)p;
    cudaGetSymbolAddress(&p, g_x0hi); __half* x0hi = (__half*)p;
    cudaGetSymbolAddress(&p, g_x0lo); __half* x0lo = (__half*)p;
    cudaGetSymbolAddress(&p, g_xg);   float* xgb = (float*)p;
    cudaGetSymbolAddress(&p, g_Bp);   uint4* bp = (uint4*)p;
    cudaGetSymbolAddress(&p, g_acc);  float* accb = (float*)p;

    cudaFuncSetAttribute(gemm_lstm<true>,  cudaFuncAttributeMaxDynamicSharedMemorySize, SMEMSZ);
    cudaFuncSetAttribute(gemm_lstm<false>, cudaFuncAttributeMaxDynamicSharedMemorySize, SMEMSZ);

    // launch 1: zero state; launch 2: prepack all weights
    zero_all<<<(LAYERS * HL + 255) / 256, 256>>>(hhi, hlo, cbuf, accb);
    prepack_all<<<BP_TOTAL / 256, 256>>>(
        (const float*)d_in[2], (const float*)d_in[3],
        (const float*)d_in[4], (const float*)d_in[5],
        (const float*)d_in[6], (const float*)d_in[7],
        (const float*)d_in[8], (const float*)d_in[9], bp);

    dim3 ggrid(4, 32);
    for (int t = 0; t < NSTEP; t++) {
        int r = t & 1, w = 1 - r;
        __half* hhr = hhi + (size_t)r * LAYERS * HL;
        __half* hhw = hhi + (size_t)w * LAYERS * HL;
        __half* hlr = hlo + (size_t)r * LAYERS * HL;
        __half* hlw = hlo + (size_t)w * LAYERS * HL;
        float* cr = cbuf + (size_t)r * LAYERS * HL;
        float* cw = cbuf + (size_t)w * LAYERS * HL;

        mask_k<<<(BB * NPOS * FC + 255) / 256, 256>>>(frames, maskp, xgb, x0hi, x0lo, t);

        gemm_lstm<true><<<ggrid, 256, SMEMSZ>>>(
            x0hi, x0lo, hhr, hlr, bp, cr, cw, hhw, hlw);
        for (int l = 1; l < LAYERS; l++) {
            gemm_lstm<false><<<ggrid, 256, SMEMSZ>>>(
                hhw + (size_t)(l - 1) * HL, hlw + (size_t)(l - 1) * HL,
                hhr + (size_t)l * HL,       hlr + (size_t)l * HL,
                bp + BP_L0_U4 + (size_t)(l - 1) * BP_LN_U4,
                cr + (size_t)l * HL, cw + (size_t)l * HL,
                hhw + (size_t)l * HL, hlw + (size_t)l * HL);
        }
        xgen_k<<<BB, 256>>>(hhw + (size_t)3 * HL, hlw + (size_t)3 * HL, Wlast, xgb, out, t);
    }

    mse_k<<<1024, 256>>>(out, frames, accb);
    heur_k<<<1, NSTEP * 16>>>(out, frames, accb);
    finalize_k<<<1, 1>>>(accb, out + (out_size - 1));
}